// round 11
// baseline (speedup 1.0000x reference)
#include <cuda_runtime.h>
#include <cuda_bf16.h>
#include <cstdint>

// Correlation via banded Gram matrices on mma.sync (HMMA) tensor cores.
// out[b, i*41+j, y, x] = (1/576)*sum_c in1[b,c,y,x]*in2[b,c,y-2(j-10),x-2(i-10)]
// in1,in2: [4,64,96,160] fp32; out: [4,1681,96,160] fp32.
//
// prep: each input row -> SW128 K-major bf16 image (hi | lo), 40KB, in g_scr.
// main: CTA=(j,y,b). smem: A image 160x128B (hi|lo), B image zero-padded to
//   240 rows (x' in [-60,180)) (hi|lo). 5 warps; warp w computes G rows
//   x in [32w,32w+32) over the 112-col padded window [32w, 32w+112):
//   2 strips of m16, 12 n8-tiles each (strip1 reuses B frags shifted by 2).
//   3 bf16 passes (hi*hi + lo*hi + hi*lo) accumulate in fp32 frags.
//   Epilogue: frags -> smem (pitch 98) -> branch-free diagonal gather.

#define D41 41
#define HH 96
#define WW 160
#define CC 64
#define OSTRI (D41*HH*WW)
#define ROWB 40960            // per-row image bytes (hi 20480 + lo 20480)

#define SM_A   0              // A hi [0,20480), A lo [20480,40960)
#define SM_B   40960          // B hi [40960,71680), B lo [71680,102400)
#define BROWS  30720          // 240*128
#define SMEM_BYTES 102400
#define PITCH 98

__device__ __align__(1024) unsigned char g_scr[(size_t)2 * 4 * HH * ROWB];

__device__ __forceinline__ uint32_t swz(uint32_t o) { return o ^ ((o >> 3) & 0x70); }

__device__ __forceinline__ uint32_t smem_u32(const void* p) {
    uint32_t a;
    asm("{ .reg .u64 t; cvta.to.shared.u64 t, %1; cvt.u32.u64 %0, t; }"
        : "=r"(a) : "l"(p));
    return a;
}

__device__ __forceinline__ void ldsm4(uint32_t* r, uint32_t a) {
    asm volatile("ldmatrix.sync.aligned.m8n8.x4.shared.b16 {%0,%1,%2,%3}, [%4];"
                 : "=r"(r[0]), "=r"(r[1]), "=r"(r[2]), "=r"(r[3]) : "r"(a));
}
__device__ __forceinline__ void ldsm2(uint32_t* r, uint32_t a) {
    asm volatile("ldmatrix.sync.aligned.m8n8.x2.shared.b16 {%0,%1}, [%2];"
                 : "=r"(r[0]), "=r"(r[1]) : "r"(a));
}
__device__ __forceinline__ void mma16816(float* d, const uint32_t* a, const uint32_t* b) {
    asm volatile(
        "mma.sync.aligned.m16n8k16.row.col.f32.bf16.bf16.f32 "
        "{%0,%1,%2,%3},{%4,%5,%6,%7},{%8,%9},{%0,%1,%2,%3};"
        : "+f"(d[0]), "+f"(d[1]), "+f"(d[2]), "+f"(d[3])
        : "r"(a[0]), "r"(a[1]), "r"(a[2]), "r"(a[3]), "r"(b[0]), "r"(b[1]));
}

// ---------- prep: fp32 rows -> swizzled bf16 hi/lo K-major images ----------
__global__ void __launch_bounds__(256)
prep_kernel(const float* __restrict__ in1, const float* __restrict__ in2)
{
    __shared__ uint32_t th[160 * 33];
    __shared__ uint32_t tl[160 * 33];
    const int y = blockIdx.x, b = blockIdx.y, w = blockIdx.z;
    const float* src = (w ? in2 : in1) + ((size_t)(b * CC) * HH + y) * WW;
    unsigned char* dst = g_scr + (size_t)((w * 4 + b) * HH + y) * ROWB;
    const int t = threadIdx.x;

    if (t < WW) {
#pragma unroll 4
        for (int c2 = 0; c2 < 32; ++c2) {
            float v0 = src[(size_t)(2 * c2) * (HH * WW) + t];
            float v1 = src[(size_t)(2 * c2 + 1) * (HH * WW) + t];
            __nv_bfloat16 h0 = __float2bfloat16(v0);
            __nv_bfloat16 h1 = __float2bfloat16(v1);
            float l0 = v0 - __bfloat162float(h0);
            float l1 = v1 - __bfloat162float(h1);
            uint32_t hp = ((uint32_t)__bfloat16_as_ushort(h1) << 16) |
                          (uint32_t)__bfloat16_as_ushort(h0);
            uint32_t lp;
            asm("cvt.rn.bf16x2.f32 %0, %1, %2;" : "=r"(lp) : "f"(l1), "f"(l0));
            th[t * 33 + c2] = hp;
            tl[t * 33 + c2] = lp;
        }
    }
    __syncthreads();
    for (int idx = t; idx < 160 * 32; idx += 256) {
        int x = idx >> 5, c2 = idx & 31;
        uint32_t o = swz((uint32_t)(x * 128 + c2 * 4));
        *reinterpret_cast<uint32_t*>(dst + o) = th[x * 33 + c2];
        *reinterpret_cast<uint32_t*>(dst + 20480 + o) = tl[x * 33 + c2];
    }
}

// ---------- main ----------
extern __shared__ __align__(1024) unsigned char smem[];

__global__ void __launch_bounds__(160, 2)
corr_main(float* __restrict__ out)
{
    const int j = blockIdx.x, y = blockIdx.y, b = blockIdx.z;
    const int tid = threadIdx.x;
    const int wid = tid >> 5, lid = tid & 31;
    const int y2 = y - 2 * (j - 10);
    const int obase = ((b * (D41 * D41) + j) * HH + y) * WW;

    if (y2 < 0 || y2 >= HH) {
        const float4 z = make_float4(0.f, 0.f, 0.f, 0.f);
        for (int idx = tid; idx < D41 * (WW / 4); idx += 160) {
            int i = idx / (WW / 4), v = idx - i * (WW / 4);
            *reinterpret_cast<float4*>(out + obase + i * OSTRI + v * 4) = z;
        }
        return;
    }

    // ---- fill smem images ----
    {
        // A: raw copy (same row indices -> swizzle preserved), 40KB
        const uint4* asrc = reinterpret_cast<const uint4*>(
            g_scr + (size_t)(b * HH + y) * ROWB);
        uint4* dA = reinterpret_cast<uint4*>(smem + SM_A);
        for (int idx = tid; idx < 2560; idx += 160) dA[idx] = asrc[idx];

        // B: rows shift by +60 -> re-swizzle per 16B chunk.
        // 2560 chunks total = hi 1280 (idx<1280) + lo 1280 (idx>=1280).
        const unsigned char* bsrc = g_scr + (size_t)((4 + b) * HH + y2) * ROWB;
        for (int idx = tid; idx < 2560; idx += 160) {
            int h = (idx >= 1280);
            int rem = h ? (idx - 1280) : idx;
            int x = rem >> 3, u = rem & 7;
            uint4 v = *reinterpret_cast<const uint4*>(
                bsrc + h * 20480 + swz((uint32_t)(x * 128 + u * 16)));
            *reinterpret_cast<uint4*>(
                smem + SM_B + h * BROWS + swz((uint32_t)((x + 60) * 128 + u * 16))) = v;
        }
        // B zero pads: rows [0,60) and [220,240), hi+lo
        const uint4 z = make_uint4(0, 0, 0, 0);
        for (int idx = tid; idx < 1280; idx += 160) {
            int h = idx / 640, rem = idx - h * 640;
            int p = rem >> 3, u = rem & 7;
            int r = (p < 60) ? p : (p + 160);   // 220..239
            *reinterpret_cast<uint4*>(smem + SM_B + h * BROWS + r * 128 + u * 16) = z;
        }
    }
    __syncthreads();

    const uint32_t sb = smem_u32(smem);
    const int w = wid;                       // 0..4, x block [32w, 32w+32)

    // lane-constant address pieces
    const uint32_t xr  = (uint32_t)((lid & 7) << 4);
    const uint32_t caA = (uint32_t)(16 * (lid >> 4));
    const uint32_t caB = (uint32_t)(16 * ((lid >> 3) & 1));
    const uint32_t rA0 = (uint32_t)((32 * w + (lid & 15)) * 128);
    const uint32_t rB0 = (uint32_t)((32 * w + (lid & 7)) * 128);

    float acc[2][12][4];
#pragma unroll
    for (int s = 0; s < 2; ++s)
#pragma unroll
        for (int t = 0; t < 12; ++t)
#pragma unroll
            for (int r = 0; r < 4; ++r) acc[s][t][r] = 0.f;

#pragma unroll 1
    for (int pass = 0; pass < 3; ++pass) {
        const uint32_t Ab = sb + SM_A + (pass == 1 ? 20480u : 0u);
        const uint32_t Bb = sb + SM_B + (pass == 2 ? (uint32_t)BROWS : 0u);
#pragma unroll
        for (int k = 0; k < 4; ++k) {
            const uint32_t cA = (caA + 32u * k) ^ xr;
            const uint32_t cB = (caB + 32u * k) ^ xr;
            uint32_t a0[4], a1[4];
            ldsm4(a0, Ab + rA0 + cA);
            ldsm4(a1, Ab + rA0 + 2048u + cA);
            uint32_t bf[14][2];
#pragma unroll
            for (int t = 0; t < 14; ++t)
                ldsm2(bf[t], Bb + rB0 + (uint32_t)(t * 1024) + cB);
#pragma unroll
            for (int t = 0; t < 12; ++t) mma16816(acc[0][t], a0, bf[t]);
#pragma unroll
            for (int t = 0; t < 12; ++t) mma16816(acc[1][t], a1, bf[t + 2]);
        }
    }

    __syncthreads();    // images dead after this point; stage C into smem

    float* stg = reinterpret_cast<float*>(smem);
    {
        const int g = lid >> 2;
        const int n0 = 2 * (lid & 3);
#pragma unroll
        for (int s = 0; s < 2; ++s) {
            const int xlo = 32 * w + 16 * s + g;
#pragma unroll
            for (int t = 0; t < 12; ++t) {
                const int n = 8 * t + n0;
                *reinterpret_cast<float2*>(stg + xlo * PITCH + n) =
                    make_float2(acc[s][t][0], acc[s][t][1]);
                *reinterpret_cast<float2*>(stg + (xlo + 8) * PITCH + n) =
                    make_float2(acc[s][t][2], acc[s][t][3]);
            }
        }
    }
    __syncthreads();

    // gather: out[i, x] = G[x, x+20-2i] / 576;  stage col = (x&15) + 80 - 2i
    {
        const int x = tid;                 // 160 threads
        const float scl = 1.0f / 576.0f;
        const float* row = stg + x * PITCH + (x & 15) + 80;
        float* op = out + obase + x;
#pragma unroll 1
        for (int i = 0; i < D41; ++i)
            op[i * OSTRI] = row[-2 * i] * scl;
    }
}

extern "C" void kernel_launch(void* const* d_in, const int* in_sizes, int n_in,
                              void* d_out, int out_size) {
    const float* in1 = (const float*)d_in[0];
    const float* in2 = (const float*)d_in[1];
    float* out = (float*)d_out;

    cudaFuncSetAttribute(corr_main,
                         cudaFuncAttributeMaxDynamicSharedMemorySize, SMEM_BYTES);

    prep_kernel<<<dim3(HH, 4, 2), 256>>>(in1, in2);
    corr_main<<<dim3(D41, HH, 4), 160, SMEM_BYTES>>>(out);
}

// round 12
// speedup vs baseline: 3.8944x; 3.8944x over previous
#include <cuda_runtime.h>
#include <cuda_fp16.h>
#include <cstdint>

// Correlation via banded Gram matrices on mma.sync fp16 HMMA (single pass).
// out[b, i*41+j, y, x] = (1/576)*sum_c in1[b,c,y,x]*in2[b,c,y-2(j-10),x-2(i-10)]
// in1,in2: [4,64,96,160] fp32; out: [4,1681,96,160] fp32.
//
// prep: each input row -> SW128 K-major fp16 image (20KB) in g_scr.
// main: CTA=(j,y,b), 320 thr = 10 warps. smem: A image 160x128B,
//   B image zero-padded to 240 rows (x' in [-60,180)). Warp (w,h):
//   m-block w (x in [32w,32w+32), 2 strips of m16), n-half h (6 of 12 n8-tiles).
//   Single fp16 pass, fp32 accum (inputs ~N(0,1): fp16-safe, ~1.5e-4 rel).
//   Epilogue: frags -> smem stage (pitch 98) -> branch-free diagonal gather.

#define D41 41
#define HH 96
#define WW 160
#define CC 64
#define OSTRI (D41*HH*WW)
#define ROWB 20480            // per-row fp16 image bytes (160 x 128B)

#define SM_A   0              // [0, 20480)
#define SM_B   20480          // [20480, 51200): 240 rows x 128B
#define SMEM_BYTES 62976      // stage (160*98*4 = 62720) reuses whole smem
#define PITCH 98

__device__ __align__(1024) unsigned char g_scr[(size_t)2 * 4 * HH * ROWB];

__device__ __forceinline__ uint32_t swz(uint32_t o) { return o ^ ((o >> 3) & 0x70); }

__device__ __forceinline__ uint32_t smem_u32(const void* p) {
    uint32_t a;
    asm("{ .reg .u64 t; cvta.to.shared.u64 t, %1; cvt.u32.u64 %0, t; }"
        : "=r"(a) : "l"(p));
    return a;
}

__device__ __forceinline__ void ldsm4(uint32_t* r, uint32_t a) {
    asm volatile("ldmatrix.sync.aligned.m8n8.x4.shared.b16 {%0,%1,%2,%3}, [%4];"
                 : "=r"(r[0]), "=r"(r[1]), "=r"(r[2]), "=r"(r[3]) : "r"(a));
}
__device__ __forceinline__ void ldsm2(uint32_t* r, uint32_t a) {
    asm volatile("ldmatrix.sync.aligned.m8n8.x2.shared.b16 {%0,%1}, [%2];"
                 : "=r"(r[0]), "=r"(r[1]) : "r"(a));
}
__device__ __forceinline__ void mma16816(float* d, const uint32_t* a, const uint32_t* b) {
    asm volatile(
        "mma.sync.aligned.m16n8k16.row.col.f32.f16.f16.f32 "
        "{%0,%1,%2,%3},{%4,%5,%6,%7},{%8,%9},{%0,%1,%2,%3};"
        : "+f"(d[0]), "+f"(d[1]), "+f"(d[2]), "+f"(d[3])
        : "r"(a[0]), "r"(a[1]), "r"(a[2]), "r"(a[3]), "r"(b[0]), "r"(b[1]));
}

// ---------- prep: fp32 rows -> swizzled fp16 K-major images ----------
__global__ void __launch_bounds__(256)
prep_kernel(const float* __restrict__ in1, const float* __restrict__ in2)
{
    __shared__ uint32_t th[160 * 33];
    const int y = blockIdx.x, b = blockIdx.y, w = blockIdx.z;
    const float* src = (w ? in2 : in1) + ((size_t)(b * CC) * HH + y) * WW;
    unsigned char* dst = g_scr + (size_t)((w * 4 + b) * HH + y) * ROWB;
    const int t = threadIdx.x;

    if (t < WW) {
#pragma unroll 4
        for (int c2 = 0; c2 < 32; ++c2) {
            float v0 = src[(size_t)(2 * c2) * (HH * WW) + t];
            float v1 = src[(size_t)(2 * c2 + 1) * (HH * WW) + t];
            __half2 h = __floats2half2_rn(v0, v1);   // v0 lo, v1 hi
            th[t * 33 + c2] = *reinterpret_cast<uint32_t*>(&h);
        }
    }
    __syncthreads();
    for (int idx = t; idx < 160 * 32; idx += 256) {
        int x = idx >> 5, c2 = idx & 31;
        uint32_t o = swz((uint32_t)(x * 128 + c2 * 4));
        *reinterpret_cast<uint32_t*>(dst + o) = th[x * 33 + c2];
    }
}

// ---------- main ----------
extern __shared__ __align__(1024) unsigned char smem[];

__global__ void __launch_bounds__(320, 2)
corr_main(float* __restrict__ out)
{
    const int j = blockIdx.x, y = blockIdx.y, b = blockIdx.z;
    const int tid = threadIdx.x;
    const int wid = tid >> 5, lid = tid & 31;
    const int y2 = y - 2 * (j - 10);
    const int obase = ((b * (D41 * D41) + j) * HH + y) * WW;

    if (y2 < 0 || y2 >= HH) {
        const float4 z = make_float4(0.f, 0.f, 0.f, 0.f);
        for (int idx = tid; idx < D41 * (WW / 4); idx += 320) {
            int i = idx / (WW / 4), v = idx - i * (WW / 4);
            *reinterpret_cast<float4*>(out + obase + i * OSTRI + v * 4) = z;
        }
        return;
    }

    // ---- fill smem images ----
    {
        // A: raw copy (row indices identical -> swizzle preserved), 20KB
        const uint4* asrc = reinterpret_cast<const uint4*>(
            g_scr + (size_t)(b * HH + y) * ROWB);
        uint4* dA = reinterpret_cast<uint4*>(smem + SM_A);
#pragma unroll
        for (int it = 0; it < 4; ++it) dA[tid + 320 * it] = asrc[tid + 320 * it];

        // B: rows shift by +60 -> re-swizzle per 16B chunk (1280 chunks)
        const unsigned char* bsrc = g_scr + (size_t)((4 + b) * HH + y2) * ROWB;
#pragma unroll
        for (int it = 0; it < 4; ++it) {
            int idx = tid + 320 * it;
            int x = idx >> 3, u = idx & 7;
            uint4 v = *reinterpret_cast<const uint4*>(
                bsrc + swz((uint32_t)(x * 128 + u * 16)));
            *reinterpret_cast<uint4*>(
                smem + SM_B + swz((uint32_t)((x + 60) * 128 + u * 16))) = v;
        }
        // B zero pads: rows [0,60) and [220,240) (640 chunks)
        const uint4 z = make_uint4(0, 0, 0, 0);
#pragma unroll
        for (int it = 0; it < 2; ++it) {
            int idx = tid + 320 * it;
            int p = idx >> 3, u = idx & 7;
            int r = (p < 60) ? p : (p + 160);   // 220..239
            *reinterpret_cast<uint4*>(smem + SM_B + r * 128 + u * 16) = z;
        }
    }
    __syncthreads();

    const uint32_t sb = smem_u32(smem);
    const int w = wid >> 1;                  // 0..4: x block [32w, 32w+32)
    const int h = wid & 1;                   // n-half: acc tiles T in [6h, 6h+6)

    // lane-constant address pieces (validated layout from bf16 kernel)
    const uint32_t xr  = (uint32_t)((lid & 7) << 4);
    const uint32_t caA = (uint32_t)(16 * (lid >> 4));
    const uint32_t caB = (uint32_t)(16 * ((lid >> 3) & 1));
    const uint32_t rA0 = (uint32_t)((32 * w + (lid & 15)) * 128);
    const uint32_t rB0 = (uint32_t)((32 * w + (lid & 7)) * 128);

    const uint32_t Ab = sb + SM_A;
    const uint32_t Bb = sb + SM_B + rB0 + (uint32_t)(6 * h * 1024);

    float acc[2][6][4];
#pragma unroll
    for (int s = 0; s < 2; ++s)
#pragma unroll
        for (int t = 0; t < 6; ++t)
#pragma unroll
            for (int r = 0; r < 4; ++r) acc[s][t][r] = 0.f;

#pragma unroll
    for (int k = 0; k < 4; ++k) {
        const uint32_t cA = (caA + 32u * k) ^ xr;
        const uint32_t cB = (caB + 32u * k) ^ xr;
        uint32_t a0[4], a1[4];
        ldsm4(a0, Ab + rA0 + cA);
        ldsm4(a1, Ab + rA0 + 2048u + cA);
        uint32_t bf[8][2];
#pragma unroll
        for (int u = 0; u < 8; ++u)
            ldsm2(bf[u], Bb + (uint32_t)(u * 1024) + cB);
#pragma unroll
        for (int t = 0; t < 6; ++t) mma16816(acc[0][t], a0, bf[t]);
#pragma unroll
        for (int t = 0; t < 6; ++t) mma16816(acc[1][t], a1, bf[t + 2]);
    }

    __syncthreads();    // images dead; stage C into smem

    float* stg = reinterpret_cast<float*>(smem);
    {
        const int g = lid >> 2;
        const int n0 = 2 * (lid & 3);
#pragma unroll
        for (int s = 0; s < 2; ++s) {
            const int xlo = 32 * w + 16 * s + g;
#pragma unroll
            for (int t = 0; t < 6; ++t) {
                const int n = 8 * (6 * h + t) + n0;
                *reinterpret_cast<float2*>(stg + xlo * PITCH + n) =
                    make_float2(acc[s][t][0], acc[s][t][1]);
                *reinterpret_cast<float2*>(stg + (xlo + 8) * PITCH + n) =
                    make_float2(acc[s][t][2], acc[s][t][3]);
            }
        }
    }
    __syncthreads();

    // gather: out[i, x] = G[x, x+20-2i] / 576;  stage col = (x&15) + 80 - 2i
    {
        const int x = (tid < 160) ? tid : (tid - 160);
        const int ilo = (tid < 160) ? 0 : 21;
        const int ihi = (tid < 160) ? 21 : 41;
        const float scl = 1.0f / 576.0f;
        const float* row = stg + x * PITCH + (x & 15) + 80;
        float* op = out + obase + x;
#pragma unroll 1
        for (int i = ilo; i < ihi; ++i)
            op[i * OSTRI] = row[-2 * i] * scl;
    }
}

extern "C" void kernel_launch(void* const* d_in, const int* in_sizes, int n_in,
                              void* d_out, int out_size) {
    const float* in1 = (const float*)d_in[0];
    const float* in2 = (const float*)d_in[1];
    float* out = (float*)d_out;

    cudaFuncSetAttribute(corr_main,
                         cudaFuncAttributeMaxDynamicSharedMemorySize, SMEM_BYTES);

    prep_kernel<<<dim3(HH, 4, 2), 256>>>(in1, in2);
    corr_main<<<dim3(D41, HH, 4), 320, SMEM_BYTES>>>(out);
}

// round 13
// speedup vs baseline: 5.6101x; 1.4406x over previous
#include <cuda_runtime.h>
#include <cuda_fp16.h>
#include <cstdint>

// Correlation via parity-split banded Gram matrices on fp16 mma.sync.
// out[b, i*41+j, y, x] = (1/576)*sum_c in1[b,c,y,x]*in2[b,c,y-2(j-10),x-2(i-10)]
// xp = x+20-2i has the parity of x -> split x/xp by parity: 2 banded Grams of
// 80 rows; band per m16 strip = 56 cols, every column a valid output.
//
// prep: in1 rows -> parity-permuted A images (2*80 rows x 128B fp16 K-major,
//   SW128). in2 rows -> B images (2*120 rows, u-pad +-30 baked in, zeros).
// main: CTA=(j,y,b), 320 thr = 10 warps = (parity p, strip s). Raw-copy both
//   images, warp does m16 x 56-col band x k64: 7 n8-tiles x 4 k-steps.
//   Stage frags (pitch 58) -> branch-free diagonal gather -> coalesced out.

#define D41 41
#define HH 96
#define WW 160
#define CC 64
#define OSTRI (D41*HH*WW)

#define AROWB 20480           // A image: 160 rows x 128B
#define BROWB 30720           // B image: 240 rows x 128B
#define A_TOT ((size_t)4 * HH * AROWB)

#define SM_A 0                // [0, 20480)
#define SM_B 20480            // [20480, 51200)
#define SMEM_BYTES 51200
#define PITCH 58              // stage pitch (floats); stage = 160*58*4 = 37120

__device__ __align__(1024) unsigned char g_scr[A_TOT + (size_t)4 * HH * BROWB];

__device__ __forceinline__ uint32_t swz(uint32_t o) { return o ^ ((o >> 3) & 0x70); }

__device__ __forceinline__ uint32_t smem_u32(const void* p) {
    uint32_t a;
    asm("{ .reg .u64 t; cvta.to.shared.u64 t, %1; cvt.u32.u64 %0, t; }"
        : "=r"(a) : "l"(p));
    return a;
}
__device__ __forceinline__ void ldsm4(uint32_t* r, uint32_t a) {
    asm volatile("ldmatrix.sync.aligned.m8n8.x4.shared.b16 {%0,%1,%2,%3}, [%4];"
                 : "=r"(r[0]), "=r"(r[1]), "=r"(r[2]), "=r"(r[3]) : "r"(a));
}
__device__ __forceinline__ void ldsm2(uint32_t* r, uint32_t a) {
    asm volatile("ldmatrix.sync.aligned.m8n8.x2.shared.b16 {%0,%1}, [%2];"
                 : "=r"(r[0]), "=r"(r[1]) : "r"(a));
}
__device__ __forceinline__ void mma16816(float* d, const uint32_t* a, const uint32_t* b) {
    asm volatile(
        "mma.sync.aligned.m16n8k16.row.col.f32.f16.f16.f32 "
        "{%0,%1,%2,%3},{%4,%5,%6,%7},{%8,%9},{%0,%1,%2,%3};"
        : "+f"(d[0]), "+f"(d[1]), "+f"(d[2]), "+f"(d[3])
        : "r"(a[0]), "r"(a[1]), "r"(a[2]), "r"(a[3]), "r"(b[0]), "r"(b[1]));
}

// ---------- prep: fp32 rows -> parity-permuted swizzled fp16 images ----------
__global__ void __launch_bounds__(256)
prep_kernel(const float* __restrict__ in1, const float* __restrict__ in2)
{
    __shared__ uint32_t th[160 * 33];
    const int y = blockIdx.x, b = blockIdx.y, w = blockIdx.z;
    const float* src = (w ? in2 : in1) + ((size_t)(b * CC) * HH + y) * WW;
    unsigned char* dst = w ? (g_scr + A_TOT + (size_t)(b * HH + y) * BROWB)
                           : (g_scr + (size_t)(b * HH + y) * AROWB);
    const int t = threadIdx.x;

    if (t < WW) {
#pragma unroll 4
        for (int c2 = 0; c2 < 32; ++c2) {
            float v0 = src[(size_t)(2 * c2) * (HH * WW) + t];
            float v1 = src[(size_t)(2 * c2 + 1) * (HH * WW) + t];
            __half2 h = __floats2half2_rn(v0, v1);
            th[t * 33 + c2] = *reinterpret_cast<uint32_t*>(&h);
        }
    }
    __syncthreads();

    if (w == 0) {
        // A image: row = p*80 + x/2
        for (int idx = t; idx < 160 * 32; idx += 256) {
            int x = idx >> 5, c2 = idx & 31;
            int row = (x & 1) * 80 + (x >> 1);
            *reinterpret_cast<uint32_t*>(dst + swz((uint32_t)(row * 128 + c2 * 4))) =
                th[x * 33 + c2];
        }
    } else {
        // B zero pads: per parity rows v in [0,30) u [110,120): 80 rows total
        uint32_t* d32 = reinterpret_cast<uint32_t*>(dst);
        for (int idx = t; idx < 80 * 32; idx += 256) {
            int r = idx >> 5, c2 = idx & 31;
            int p = (r >= 40), q = r - p * 40;
            int v = (q < 30) ? q : (q + 80);
            d32[(p * 120 + v) * 32 + c2] = 0;     // whole-row zero: swz-invariant
        }
        // B data: row = p*120 + (x/2 + 30)
        for (int idx = t; idx < 160 * 32; idx += 256) {
            int x = idx >> 5, c2 = idx & 31;
            int row = (x & 1) * 120 + (x >> 1) + 30;
            *reinterpret_cast<uint32_t*>(dst + swz((uint32_t)(row * 128 + c2 * 4))) =
                th[x * 33 + c2];
        }
    }
}

// ---------- main ----------
extern __shared__ __align__(1024) unsigned char smem[];

__global__ void __launch_bounds__(320, 3)
corr_main(float* __restrict__ out)
{
    const int j = blockIdx.x, y = blockIdx.y, b = blockIdx.z;
    const int tid = threadIdx.x;
    const int wid = tid >> 5, lid = tid & 31;
    const int y2 = y - 2 * (j - 10);
    const int obase = ((b * (D41 * D41) + j) * HH + y) * WW;

    if (y2 < 0 || y2 >= HH) {
        const float4 z = make_float4(0.f, 0.f, 0.f, 0.f);
        for (int idx = tid; idx < D41 * (WW / 4); idx += 320) {
            int i = idx / (WW / 4), v = idx - i * (WW / 4);
            *reinterpret_cast<float4*>(out + obase + i * OSTRI + v * 4) = z;
        }
        return;
    }

    // ---- raw-copy both images (pre-swizzled, pre-padded in prep) ----
    {
        const uint4* asrc = reinterpret_cast<const uint4*>(
            g_scr + (size_t)(b * HH + y) * AROWB);
        uint4* dA = reinterpret_cast<uint4*>(smem + SM_A);
#pragma unroll
        for (int it = 0; it < 4; ++it) dA[tid + 320 * it] = asrc[tid + 320 * it];

        const uint4* bsrc = reinterpret_cast<const uint4*>(
            g_scr + A_TOT + (size_t)((4 + b - 4) * 0 + (b * HH + y2)) * BROWB);
        uint4* dB = reinterpret_cast<uint4*>(smem + SM_B);
#pragma unroll
        for (int it = 0; it < 6; ++it) dB[tid + 320 * it] = bsrc[tid + 320 * it];
    }
    __syncthreads();

    const uint32_t sb = smem_u32(smem);
    const int s = wid >> 1;                  // strip 0..4 (rows 16s..16s+16)
    const int p = wid & 1;                   // parity

    const uint32_t xr = (uint32_t)((lid & 7) << 4);
    // A: row = p*80 + 16s + (lid&15)
    const uint32_t aRow = sb + SM_A +
        (uint32_t)((p * 80 + 16 * s + (lid & 15)) * 128);
    const uint32_t caA = (uint32_t)(16 * (lid >> 4));
    // B: base row = p*120 + 16s; ldsm4 adds 16u + (lid&7) + 8*(lid>>4)
    const uint32_t bRow = sb + SM_B +
        (uint32_t)((p * 120 + 16 * s + (lid & 7) + 8 * (lid >> 4)) * 128);
    const uint32_t bRow2 = sb + SM_B +
        (uint32_t)((p * 120 + 16 * s + 48 + (lid & 7)) * 128);
    const uint32_t caB = (uint32_t)(16 * ((lid >> 3) & 1));

    float acc[7][4];
#pragma unroll
    for (int t = 0; t < 7; ++t)
#pragma unroll
        for (int r = 0; r < 4; ++r) acc[t][r] = 0.f;

#pragma unroll
    for (int k = 0; k < 4; ++k) {
        const uint32_t cA = (caA + 32u * k) ^ xr;
        const uint32_t cB = (caB + 32u * k) ^ xr;
        uint32_t a[4];
        ldsm4(a, aRow + cA);
        uint32_t bf[14];
#pragma unroll
        for (int u = 0; u < 3; ++u)
            ldsm4(bf + 4 * u, bRow + (uint32_t)(u * 2048) + cB);
        ldsm2(bf + 12, bRow2 + cB);
#pragma unroll
        for (int t = 0; t < 7; ++t) mma16816(acc[t], a, bf + 2 * t);
    }

    __syncthreads();    // images dead; stage G band into smem

    // stage[(p*80 + xh)*PITCH + n], n = v - 16s in [0,56)
    float* stg = reinterpret_cast<float*>(smem);
    {
        const int g = lid >> 2;
        const int n0 = 2 * (lid & 3);
        const int r0 = p * 80 + 16 * s + g;
#pragma unroll
        for (int t = 0; t < 7; ++t) {
            const int n = 8 * t + n0;
            *reinterpret_cast<float2*>(stg + r0 * PITCH + n) =
                make_float2(acc[t][0], acc[t][1]);
            *reinterpret_cast<float2*>(stg + (r0 + 8) * PITCH + n) =
                make_float2(acc[t][2], acc[t][3]);
        }
    }
    __syncthreads();

    // gather: out[i, x]: x = 2xh+p; n = (xh&15) + 40 - i; row = p*80 + xh
    {
        const int x = (tid < 160) ? tid : (tid - 160);
        const int ilo = (tid < 160) ? 0 : 21;
        const int ihi = (tid < 160) ? 21 : 41;
        const int xh = x >> 1;
        const float scl = 1.0f / 576.0f;
        const float* row = stg + ((x & 1) * 80 + xh) * PITCH + (xh & 15) + 40;
        float* op = out + obase + x;
#pragma unroll 1
        for (int i = ilo; i < ihi; ++i)
            op[i * OSTRI] = row[-i] * scl;
    }
}

extern "C" void kernel_launch(void* const* d_in, const int* in_sizes, int n_in,
                              void* d_out, int out_size) {
    const float* in1 = (const float*)d_in[0];
    const float* in2 = (const float*)d_in[1];
    float* out = (float*)d_out;

    cudaFuncSetAttribute(corr_main,
                         cudaFuncAttributeMaxDynamicSharedMemorySize, SMEM_BYTES);

    prep_kernel<<<dim3(HH, 4, 2), 256>>>(in1, in2);
    corr_main<<<dim3(D41, HH, 4), 320, SMEM_BYTES>>>(out);
}

// round 15
// speedup vs baseline: 5.6205x; 1.0018x over previous
#include <cuda_runtime.h>
#include <cuda_fp16.h>
#include <cstdint>

// Correlation via parity-split banded Gram matrices on fp16 mma.sync,
// with j-batching (3 displacement-rows per CTA share the A image).
// out[b, i*41+j, y, x] = (1/576)*sum_c in1[b,c,y,x]*in2[b,c,y-2(j-10),x-2(i-10)]
//
// prep: in1 rows -> parity-permuted A images (2*80 rows x 128B fp16 K-major,
//   SW128). in2 rows -> B images (2*120 rows, u-pad +-30 baked in).
// main: CTA=(jg,y,b), jg in [0,14): j = 3jg..(3jg+2) (jg=13: 2 js).
//   A image copied once; per j: copy B image, 10 warps = (parity p, strip s),
//   warp does m16 x 56-col band x k64 (7 n8 x 4 k). Stage (pitch 58, in the
//   B overlay) -> branch-free diagonal gather -> coalesced stores.

#define D41 41
#define HH 96
#define WW 160
#define CC 64
#define OSTRI (D41*HH*WW)

#define AROWB 20480           // A image: 160 rows x 128B
#define BROWB 30720           // B image: 240 rows x 128B
#define A_TOT ((size_t)4 * HH * AROWB)

#define SM_A   0              // [0, 20480) persistent per CTA
#define SM_B   20480          // B image [20480, 51200); stage overlays here too
#define SMEM_BYTES 57600      // 20480 + stage 37120
#define PITCH 58

__device__ __align__(1024) unsigned char g_scr[A_TOT + (size_t)4 * HH * BROWB];

__device__ __forceinline__ uint32_t swz(uint32_t o) { return o ^ ((o >> 3) & 0x70); }

__device__ __forceinline__ uint32_t smem_u32(const void* p) {
    uint32_t a;
    asm("{ .reg .u64 t; cvta.to.shared.u64 t, %1; cvt.u32.u64 %0, t; }"
        : "=r"(a) : "l"(p));
    return a;
}
__device__ __forceinline__ void ldsm4(uint32_t* r, uint32_t a) {
    asm volatile("ldmatrix.sync.aligned.m8n8.x4.shared.b16 {%0,%1,%2,%3}, [%4];"
                 : "=r"(r[0]), "=r"(r[1]), "=r"(r[2]), "=r"(r[3]) : "r"(a));
}
__device__ __forceinline__ void ldsm2(uint32_t* r, uint32_t a) {
    asm volatile("ldmatrix.sync.aligned.m8n8.x2.shared.b16 {%0,%1}, [%2];"
                 : "=r"(r[0]), "=r"(r[1]) : "r"(a));
}
__device__ __forceinline__ void mma16816(float* d, const uint32_t* a, const uint32_t* b) {
    asm volatile(
        "mma.sync.aligned.m16n8k16.row.col.f32.f16.f16.f32 "
        "{%0,%1,%2,%3},{%4,%5,%6,%7},{%8,%9},{%0,%1,%2,%3};"
        : "+f"(d[0]), "+f"(d[1]), "+f"(d[2]), "+f"(d[3])
        : "r"(a[0]), "r"(a[1]), "r"(a[2]), "r"(a[3]), "r"(b[0]), "r"(b[1]));
}

// ---------- prep: fp32 rows -> parity-permuted swizzled fp16 images ----------
__global__ void __launch_bounds__(256)
prep_kernel(const float* __restrict__ in1, const float* __restrict__ in2)
{
    __shared__ uint32_t th[160 * 33];
    const int y = blockIdx.x, b = blockIdx.y, w = blockIdx.z;
    const float* src = (w ? in2 : in1) + ((size_t)(b * CC) * HH + y) * WW;
    unsigned char* dst = w ? (g_scr + A_TOT + (size_t)(b * HH + y) * BROWB)
                           : (g_scr + (size_t)(b * HH + y) * AROWB);
    const int t = threadIdx.x;

    if (t < WW) {
#pragma unroll 4
        for (int c2 = 0; c2 < 32; ++c2) {
            float v0 = src[(size_t)(2 * c2) * (HH * WW) + t];
            float v1 = src[(size_t)(2 * c2 + 1) * (HH * WW) + t];
            __half2 h = __floats2half2_rn(v0, v1);
            th[t * 33 + c2] = *reinterpret_cast<uint32_t*>(&h);
        }
    }
    __syncthreads();

    if (w == 0) {
        for (int idx = t; idx < 160 * 32; idx += 256) {
            int x = idx >> 5, c2 = idx & 31;
            int row = (x & 1) * 80 + (x >> 1);
            *reinterpret_cast<uint32_t*>(dst + swz((uint32_t)(row * 128 + c2 * 4))) =
                th[x * 33 + c2];
        }
    } else {
        uint32_t* d32 = reinterpret_cast<uint32_t*>(dst);
        for (int idx = t; idx < 80 * 32; idx += 256) {
            int r = idx >> 5, c2 = idx & 31;
            int p = (r >= 40), q = r - p * 40;
            int v = (q < 30) ? q : (q + 80);
            d32[(p * 120 + v) * 32 + c2] = 0;     // whole-row zero: swz-invariant
        }
        for (int idx = t; idx < 160 * 32; idx += 256) {
            int x = idx >> 5, c2 = idx & 31;
            int row = (x & 1) * 120 + (x >> 1) + 30;
            *reinterpret_cast<uint32_t*>(dst + swz((uint32_t)(row * 128 + c2 * 4))) =
                th[x * 33 + c2];
        }
    }
}

// ---------- main ----------
extern __shared__ __align__(1024) unsigned char smem[];

__global__ void __launch_bounds__(320, 3)
corr_main(float* __restrict__ out)
{
    const int jg = blockIdx.x, y = blockIdx.y, b = blockIdx.z;
    const int tid = threadIdx.x;
    const int wid = tid >> 5, lid = tid & 31;

    // ---- A image: copy once (raw, pre-swizzled) ----
    {
        const uint4* asrc = reinterpret_cast<const uint4*>(
            g_scr + (size_t)(b * HH + y) * AROWB);
        uint4* dA = reinterpret_cast<uint4*>(smem + SM_A);
#pragma unroll
        for (int it = 0; it < 4; ++it) dA[tid + 320 * it] = asrc[tid + 320 * it];
    }

    const uint32_t sb = smem_u32(smem);
    const int s = wid >> 1;                  // strip 0..4
    const int p = wid & 1;                   // parity

    const uint32_t xr = (uint32_t)((lid & 7) << 4);
    const uint32_t aRow = sb + SM_A +
        (uint32_t)((p * 80 + 16 * s + (lid & 15)) * 128);
    const uint32_t caA = (uint32_t)(16 * (lid >> 4));
    const uint32_t bRow = sb + SM_B +
        (uint32_t)((p * 120 + 16 * s + (lid & 7) + 8 * (lid >> 4)) * 128);
    const uint32_t bRow2 = sb + SM_B +
        (uint32_t)((p * 120 + 16 * s + 48 + (lid & 7)) * 128);
    const uint32_t caB = (uint32_t)(16 * ((lid >> 3) & 1));

    float* stg = reinterpret_cast<float*>(smem + SM_B);
    const int njj = (jg == 13) ? 2 : 3;

#pragma unroll 1
    for (int jj = 0; jj < njj; ++jj) {
        const int j = 3 * jg + jj;
        const int y2 = y - 2 * (j - 10);
        const bool valid = (y2 >= 0) && (y2 < HH);
        const int obase = ((b * (D41 * D41) + j) * HH + y) * WW;

        __syncthreads();          // stage (prev j) fully read; A copy done (jj=0)

        if (valid) {
            const uint4* bsrc = reinterpret_cast<const uint4*>(
                g_scr + A_TOT + (size_t)(b * HH + y2) * BROWB);
            uint4* dB = reinterpret_cast<uint4*>(smem + SM_B);
#pragma unroll
            for (int it = 0; it < 6; ++it) dB[tid + 320 * it] = bsrc[tid + 320 * it];
        }
        __syncthreads();

        if (valid) {
            float acc[7][4];
#pragma unroll
            for (int t = 0; t < 7; ++t)
#pragma unroll
                for (int r = 0; r < 4; ++r) acc[t][r] = 0.f;

#pragma unroll
            for (int k = 0; k < 4; ++k) {
                const uint32_t cA = (caA + 32u * k) ^ xr;
                const uint32_t cB = (caB + 32u * k) ^ xr;
                uint32_t a[4];
                ldsm4(a, aRow + cA);
                uint32_t bf[14];
#pragma unroll
                for (int u = 0; u < 3; ++u)
                    ldsm4(bf + 4 * u, bRow + (uint32_t)(u * 2048) + cB);
                ldsm2(bf + 12, bRow2 + cB);
#pragma unroll
                for (int t = 0; t < 7; ++t) mma16816(acc[t], a, bf + 2 * t);
            }

            __syncthreads();      // B image fully consumed; stage may overwrite

            const int g = lid >> 2;
            const int n0 = 2 * (lid & 3);
            const int r0 = p * 80 + 16 * s + g;
#pragma unroll
            for (int t = 0; t < 7; ++t) {
                const int n = 8 * t + n0;
                *reinterpret_cast<float2*>(stg + r0 * PITCH + n) =
                    make_float2(acc[t][0], acc[t][1]);
                *reinterpret_cast<float2*>(stg + (r0 + 8) * PITCH + n) =
                    make_float2(acc[t][2], acc[t][3]);
            }
            __syncthreads();

            // gather: x = 2xh+p; col = (xh&15) + 40 - i; row = p*80 + xh
            const int x = (tid < 160) ? tid : (tid - 160);
            const int ilo = (tid < 160) ? 0 : 21;
            const int ihi = (tid < 160) ? 21 : 41;
            const int xh = x >> 1;
            const float scl = 1.0f / 576.0f;
            const float* row = stg + ((x & 1) * 80 + xh) * PITCH + (xh & 15) + 40;
            float* op = out + obase + x;
#pragma unroll 1
            for (int i = ilo; i < ihi; ++i)
                op[i * OSTRI] = row[-i] * scl;
        } else {
            __syncthreads();      // match the two syncs of the valid path
            __syncthreads();
            const float4 z = make_float4(0.f, 0.f, 0.f, 0.f);
            for (int idx = tid; idx < D41 * (WW / 4); idx += 320) {
                int i = idx / (WW / 4), v = idx - i * (WW / 4);
                *reinterpret_cast<float4*>(out + obase + i * OSTRI + v * 4) = z;
            }
        }
    }
}

extern "C" void kernel_launch(void* const* d_in, const int* in_sizes, int n_in,
                              void* d_out, int out_size) {
    const float* in1 = (const float*)d_in[0];
    const float* in2 = (const float*)d_in[1];
    float* out = (float*)d_out;

    cudaFuncSetAttribute(corr_main,
                         cudaFuncAttributeMaxDynamicSharedMemorySize, SMEM_BYTES);

    prep_kernel<<<dim3(HH, 4, 2), 256>>>(in1, in2);
    corr_main<<<dim3(14, HH, 4), 320, SMEM_BYTES>>>(out);
}